// round 4
// baseline (speedup 1.0000x reference)
#include <cuda_runtime.h>

#define RB 64
#define RT 2048
#define RD 256
#define RV 256

// ---- device-global scratch (allocation-free per harness rules) ----
static __device__ float g_EWx[RV * RD];                 // E @ Wx^T   [tok][e]
static __device__ float g_EWg[RV * RD];                 // sigmoid(E @ Wz^T)
static __device__ float g_y[(size_t)RB * RT * RD];      // gated hidden states

// ============================================================
// Kernel 1: token tables.  EWx[v][e] = sum_d E[v][d]*Wx[e][d],
//           EWg[v][e] = sigmoid(sum_d E[v][d]*Wz[e][d])
// grid 512 (v in [0,256), which in {0,1}), 256 threads (e)
// ============================================================
__global__ void precompute_kernel(const float* __restrict__ E,
                                  const float* __restrict__ Wxw,
                                  const float* __restrict__ Wzw) {
    __shared__ __align__(16) float er[RD];
    const int v = blockIdx.x & (RV - 1);
    const int which = blockIdx.x >> 8;
    const float* __restrict__ W = which ? Wzw : Wxw;
    const int e = threadIdx.x;
    er[e] = E[v * RD + e];
    __syncthreads();
    const float4* w4 = (const float4*)(W + e * RD);
    const float4* e4 = (const float4*)er;
    float acc = 0.f;
#pragma unroll 16
    for (int q = 0; q < RD / 4; q++) {
        float4 a = e4[q];
        float4 b = w4[q];
        acc += a.x * b.x; acc += a.y * b.y; acc += a.z * b.z; acc += a.w * b.w;
    }
    if (which) g_EWg[v * RD + e] = 1.f / (1.f + expf(-acc));
    else       g_EWx[v * RD + e] = acc;
}

// ============================================================
// Kernel 2: sequential scan. One CTA per batch element.
// 512 threads: thread t -> output j = t&255, K-half kc = t>>8.
// Wh row slice: 80 values in registers, 48 in SMEM ([k][j] layout).
// ============================================================
#define SCAN_THREADS 512
#define WREG 80
#define WSM  48
#define SM_WH 0
#define SM_H  (2 * WSM * RD)          // 24576
#define SM_PS (SM_H + RD)             // 24832
#define SCAN_SMEM_FLOATS (SM_PS + 2 * RD)
#define SCAN_SMEM_BYTES  (SCAN_SMEM_FLOATS * 4)   // 101376 B

__device__ __forceinline__ float tanh_acc(float x) {
    // abs-error ~1e-7, well-behaved regardless of fast-math flags
    x = fminf(fmaxf(x, -15.f), 15.f);
    float e = __expf(2.f * x);
    return (e - 1.f) / (e + 1.f);
}

__global__ __launch_bounds__(SCAN_THREADS, 1)
void scan_kernel(const int* __restrict__ tokens, const float* __restrict__ Whw) {
    extern __shared__ float sm[];
    float* sm_wh = sm + SM_WH;
    float* sm_h  = sm + SM_H;
    float* sm_ps = sm + SM_PS;

    const int b  = blockIdx.x;
    const int t  = threadIdx.x;
    const int j  = t & (RD - 1);
    const int kc = t >> 8;            // 0 or 1
    const int kb = kc << 7;           // 0 or 128

    // --- load my Wh[j][kb .. kb+127] slice: 80 regs + 48 smem ---
    float whr[WREG];
    const float* wrow = Whw + j * RD + kb;
#pragma unroll
    for (int q = 0; q < WREG / 4; q++) {
        float4 vv = *(const float4*)(wrow + 4 * q);
        whr[4 * q + 0] = vv.x; whr[4 * q + 1] = vv.y;
        whr[4 * q + 2] = vv.z; whr[4 * q + 3] = vv.w;
    }
#pragma unroll
    for (int i = 0; i < WSM; i++)
        sm_wh[(kc * WSM + i) * RD + j] = wrow[WREG + i];   // [k][j]: conflict-free
    if (t < RD) sm_h[t] = 0.f;
    __syncthreads();

    const int* tb = tokens + b * RT;
    float* yb = g_y + (size_t)b * RT * RD;
    const float* wsp = sm_wh + kc * WSM * RD + j;
    const float* hb  = sm_h + kb;

    int tok = tb[0];
    for (int step = 0; step < RT; step++) {
        // prefetch token-indexed rows (latency hidden under matvec)
        float wxv = 0.f, gv = 0.f;
        if (t < RD) {
            wxv = __ldg(g_EWx + tok * RD + j);
            gv  = __ldg(g_EWg + tok * RD + j);
        }
        const int ntok = (step + 1 < RT) ? tb[step + 1] : 0;

        float acc0 = 0.f, acc1 = 0.f;
        // register-resident Wh part (k = kb .. kb+79)
#pragma unroll
        for (int q = 0; q < WREG / 4; q++) {
            float4 hv = *(const float4*)(hb + 4 * q);      // warp-broadcast
            acc0 += hv.x * whr[4 * q + 0]; acc0 += hv.y * whr[4 * q + 1];
            acc0 += hv.z * whr[4 * q + 2]; acc0 += hv.w * whr[4 * q + 3];
        }
        // smem-resident Wh part (k = kb+80 .. kb+127)
#pragma unroll
        for (int q = 0; q < WSM / 4; q++) {
            float4 hv = *(const float4*)(hb + WREG + 4 * q);
            acc1 += hv.x * wsp[(4 * q + 0) * RD];
            acc1 += hv.y * wsp[(4 * q + 1) * RD];
            acc1 += hv.z * wsp[(4 * q + 2) * RD];
            acc1 += hv.w * wsp[(4 * q + 3) * RD];
        }
        sm_ps[(kc << 8) + j] = acc0 + acc1;
        __syncthreads();
        if (t < RD) {
            float hn = tanh_acc(wxv + sm_ps[j] + sm_ps[RD + j]);
            sm_h[j] = hn;                               // old h fully consumed
            yb[(size_t)step * RD + j] = hn * gv;        // coalesced 1KB STG
        }
        __syncthreads();
        tok = ntok;
    }
}

// ============================================================
// Kernel 3: tied head.  out[m][v] = sum_d Y[m][d] * E[v][d]
// 128x128x16 smem-tiled fp32 GEMM, 8x8 microtiles, 256 threads.
// grid (256/128, 131072/128)
// ============================================================
#define HT 256
__global__ __launch_bounds__(HT, 2)
void head_kernel(const float* __restrict__ E, float* __restrict__ out) {
    __shared__ __align__(16) float As[16][128 + 4];
    __shared__ __align__(16) float Bs[16][128 + 4];
    const float* __restrict__ Y = g_y;
    const int m0 = blockIdx.y * 128;
    const int n0 = blockIdx.x * 128;
    const int tid = threadIdx.x;
    const int tx = tid & 15, ty = tid >> 4;

    float c[8][8];
#pragma unroll
    for (int i = 0; i < 8; i++)
#pragma unroll
        for (int jj = 0; jj < 8; jj++) c[i][jj] = 0.f;

    for (int kk = 0; kk < RD; kk += 16) {
#pragma unroll
        for (int l = 0; l < 2; l++) {
            int idx = tid + l * HT;         // 0..511
            int m   = idx >> 2;             // 0..127
            int kq  = idx & 3;              // float4 within the 16-wide K tile
            float4 av = *(const float4*)(Y + (size_t)(m0 + m) * RD + kk + kq * 4);
            As[kq * 4 + 0][m] = av.x; As[kq * 4 + 1][m] = av.y;
            As[kq * 4 + 2][m] = av.z; As[kq * 4 + 3][m] = av.w;
            float4 bv = *(const float4*)(E + (size_t)(n0 + m) * RD + kk + kq * 4);
            Bs[kq * 4 + 0][m] = bv.x; Bs[kq * 4 + 1][m] = bv.y;
            Bs[kq * 4 + 2][m] = bv.z; Bs[kq * 4 + 3][m] = bv.w;
        }
        __syncthreads();
#pragma unroll
        for (int k = 0; k < 16; k++) {
            float a[8], bb[8];
            *(float4*)(a)      = *(const float4*)(&As[k][ty * 8]);
            *(float4*)(a + 4)  = *(const float4*)(&As[k][ty * 8 + 4]);
            *(float4*)(bb)     = *(const float4*)(&Bs[k][tx * 8]);
            *(float4*)(bb + 4) = *(const float4*)(&Bs[k][tx * 8 + 4]);
#pragma unroll
            for (int i = 0; i < 8; i++)
#pragma unroll
                for (int jj = 0; jj < 8; jj++) c[i][jj] += a[i] * bb[jj];
        }
        __syncthreads();
    }
#pragma unroll
    for (int i = 0; i < 8; i++) {
        float* orow = out + (size_t)(m0 + ty * 8 + i) * RV + n0 + tx * 8;
        *(float4*)(orow)     = make_float4(c[i][0], c[i][1], c[i][2], c[i][3]);
        *(float4*)(orow + 4) = make_float4(c[i][4], c[i][5], c[i][6], c[i][7]);
    }
}

// ============================================================
extern "C" void kernel_launch(void* const* d_in, const int* in_sizes, int n_in,
                              void* d_out, int out_size) {
    const int*   tokens = (const int*)  d_in[0];
    const float* E      = (const float*)d_in[1];
    const float* Wxw    = (const float*)d_in[2];
    const float* Whw    = (const float*)d_in[3];
    const float* Wzw    = (const float*)d_in[4];
    float* out = (float*)d_out;

    cudaFuncSetAttribute(scan_kernel,
                         cudaFuncAttributeMaxDynamicSharedMemorySize,
                         SCAN_SMEM_BYTES);

    precompute_kernel<<<2 * RV, RD>>>(E, Wxw, Wzw);
    scan_kernel<<<RB, SCAN_THREADS, SCAN_SMEM_BYTES>>>(tokens, Whw);
    head_kernel<<<dim3(RV / 128, (RB * RT) / 128), HT>>>(E, out);
}

// round 5
// speedup vs baseline: 1.0927x; 1.0927x over previous
#include <cuda_runtime.h>

#define RB 64
#define RT 2048
#define RD 256
#define RV 256

// ---- device-global scratch (allocation-free per harness rules) ----
static __device__ float g_EWx[RV * RD];                 // E @ Wx^T   [tok][e]
static __device__ float g_EWg[RV * RD];                 // sigmoid(E @ Wz^T)
static __device__ float g_y[(size_t)RB * RT * RD];      // gated hidden states

// ============================================================
// Kernel 1: token tables (V=256 -> projections depend only on token id)
// ============================================================
__global__ void precompute_kernel(const float* __restrict__ E,
                                  const float* __restrict__ Wxw,
                                  const float* __restrict__ Wzw) {
    __shared__ __align__(16) float er[RD];
    const int v = blockIdx.x & (RV - 1);
    const int which = blockIdx.x >> 8;
    const float* __restrict__ W = which ? Wzw : Wxw;
    const int e = threadIdx.x;
    er[e] = E[v * RD + e];
    __syncthreads();
    const float4* w4 = (const float4*)(W + e * RD);
    const float4* e4 = (const float4*)er;
    float acc = 0.f;
#pragma unroll 16
    for (int q = 0; q < RD / 4; q++) {
        float4 a = e4[q];
        float4 b = w4[q];
        acc += a.x * b.x; acc += a.y * b.y; acc += a.z * b.z; acc += a.w * b.w;
    }
    if (which) g_EWg[v * RD + e] = 1.f / (1.f + expf(-acc));
    else       g_EWx[v * RD + e] = acc;
}

// ============================================================
// Kernel 2: sequential scan, 2-CTA cluster per batch element.
// CTA c owns K-columns [c*128, c*128+128) of Wh and rows [c*128,+128) of h.
// 512 threads: j = t&255 (output row), kc = t>>8 (which 64-wide K chunk).
// Wh slice (64 floats/thread) lives entirely in registers.
// Per step: local matvec partials -> DSMEM exchange of the peer's half
// (512 B) with double-buffered count-128 mbarriers -> local tanh -> y.
// ============================================================
#define SCAN_THREADS 512
#define SCAN_PAD_BYTES (120 * 1024)   // occupancy limiter: 1 CTA/SM

__device__ __forceinline__ float tanh_acc(float x) {
    x = fminf(fmaxf(x, -15.f), 15.f);
    float e = __expf(2.f * x);
    return (e - 1.f) / (e + 1.f);
}

__device__ __forceinline__ unsigned smem_u32(const void* p) {
    return (unsigned)__cvta_generic_to_shared(p);
}

__global__ __launch_bounds__(SCAN_THREADS, 1) __cluster_dims__(2, 1, 1)
void scan_kernel(const int* __restrict__ tokens, const float* __restrict__ Whw) {
    __shared__ __align__(16) float sm_h[128];          // own half of h
    __shared__ __align__(16) float sm_ps[2 * RD];      // partials [kc][j]
    __shared__ __align__(16) float sm_recv[2][128];    // peer partial, dbl-buf
    __shared__ __align__(8)  unsigned long long mbar[2];
    extern __shared__ float sm_pad[];                  // unused (occupancy)

    const int b    = blockIdx.x >> 1;
    const int c    = blockIdx.x & 1;       // cluster rank
    const int peer = c ^ 1;
    const int t  = threadIdx.x;
    const int j  = t & (RD - 1);
    const int kc = t >> 8;                 // 0 or 1

    // ---- init mbarriers (count = 128 arrivals per phase) ----
    if (t == 0) {
        unsigned m0 = smem_u32(&mbar[0]);
        unsigned m1 = smem_u32(&mbar[1]);
        asm volatile("mbarrier.init.shared.b64 [%0], 128;" :: "r"(m0) : "memory");
        asm volatile("mbarrier.init.shared.b64 [%0], 128;" :: "r"(m1) : "memory");
    }
    if (t < 128) sm_h[t] = 0.f;
    __syncthreads();
    // cluster barrier: peers' mbarriers must be live before any remote arrive
    asm volatile("barrier.cluster.arrive.aligned;" ::: "memory");
    asm volatile("barrier.cluster.wait.aligned;"   ::: "memory");

    // ---- load my Wh[j][c*128 + kc*64 .. +64) slice into registers ----
    float whr[64];
    {
        const float* wrow = Whw + j * RD + c * 128 + kc * 64;
#pragma unroll
        for (int q = 0; q < 16; q++) {
            float4 vv = *(const float4*)(wrow + 4 * q);
            whr[4 * q + 0] = vv.x; whr[4 * q + 1] = vv.y;
            whr[4 * q + 2] = vv.z; whr[4 * q + 3] = vv.w;
        }
    }

    // remote addresses in peer's SMEM
    unsigned rmbar[2], rrecv[2];
    {
        unsigned a0 = smem_u32(&mbar[0]), a1 = smem_u32(&mbar[1]);
        asm("mapa.shared::cluster.u32 %0, %1, %2;" : "=r"(rmbar[0]) : "r"(a0), "r"(peer));
        asm("mapa.shared::cluster.u32 %0, %1, %2;" : "=r"(rmbar[1]) : "r"(a1), "r"(peer));
        if (t < 128) {
            unsigned b0 = smem_u32(&sm_recv[0][t]);
            unsigned b1 = smem_u32(&sm_recv[1][t]);
            asm("mapa.shared::cluster.u32 %0, %1, %2;" : "=r"(rrecv[0]) : "r"(b0), "r"(peer));
            asm("mapa.shared::cluster.u32 %0, %1, %2;" : "=r"(rrecv[1]) : "r"(b1), "r"(peer));
        }
    }
    const unsigned lmbar0 = smem_u32(&mbar[0]);
    const unsigned lmbar1 = smem_u32(&mbar[1]);

    const int*   tb = tokens + b * RT;
    float*       yb = g_y + (size_t)b * RT * RD;
    const float* hb = sm_h + kc * 64;
    const int    own0  = c * 128;          // my j/k base
    const int    peer0 = peer * 128;

    int ph0 = 0, ph1 = 0;                  // phase parity per buffer
    int tok = tb[0];
    for (int step = 0; step < RT; step++) {
        // prefetch token-indexed rows for my half (hidden under matvec)
        float wxv = 0.f, gv = 0.f;
        if (t < 128) {
            wxv = __ldg(g_EWx + tok * RD + own0 + t);
            gv  = __ldg(g_EWg + tok * RD + own0 + t);
        }
        const int ntok = (step + 1 < RT) ? tb[step + 1] : 0;

        // register matvec: 64 FMAs over my K chunk
        float a0 = 0.f, a1 = 0.f, a2 = 0.f, a3 = 0.f;
#pragma unroll
        for (int q = 0; q < 16; q++) {
            float4 hv = *(const float4*)(hb + 4 * q);   // warp-broadcast LDS
            a0 += hv.x * whr[4 * q + 0];
            a1 += hv.y * whr[4 * q + 1];
            a2 += hv.z * whr[4 * q + 2];
            a3 += hv.w * whr[4 * q + 3];
        }
        sm_ps[(kc << 8) + j] = (a0 + a1) + (a2 + a3);
        __syncthreads();

        const int buf = step & 1;
        const unsigned lmb = buf ? lmbar1 : lmbar0;
        float own_p = 0.f;
        if (t < 128) {
            // send peer its half of my partial, release-arrive on peer mbar
            float ps = sm_ps[peer0 + t] + sm_ps[RD + peer0 + t];
            asm volatile("st.shared::cluster.f32 [%0], %1;"
                         :: "r"(rrecv[buf]), "f"(ps) : "memory");
            asm volatile("mbarrier.arrive.release.cluster.shared::cluster.b64 _, [%0];"
                         :: "r"(rmbar[buf]) : "memory");
            own_p = sm_ps[own0 + t] + sm_ps[RD + own0 + t];
            // wait for the peer's 128 arrivals (acquire orders its stores)
            int par = buf ? ph1 : ph0;
            unsigned done;
            do {
                asm volatile(
                    "{.reg .pred p;\n\t"
                    "mbarrier.try_wait.parity.acquire.cluster.shared::cta.b64 p, [%1], %2, 0x989680;\n\t"
                    "selp.b32 %0, 1, 0, p;}"
                    : "=r"(done) : "r"(lmb), "r"((unsigned)par) : "memory");
            } while (!done);
            float hn = tanh_acc(wxv + own_p + sm_recv[buf][t]);
            sm_h[t] = hn;
            yb[(size_t)step * RD + own0 + t] = hn * gv;   // coalesced 512B
        }
        if (buf) ph1 ^= 1; else ph0 ^= 1;
        __syncthreads();
        tok = ntok;
    }

    // drain: no CTA exits while the peer might still arrive on its mbars
    asm volatile("barrier.cluster.arrive.aligned;" ::: "memory");
    asm volatile("barrier.cluster.wait.aligned;"   ::: "memory");
    (void)sm_pad;
}

// ============================================================
// Kernel 3: tied head.  out[m][v] = sum_d Y[m][d] * E[v][d]
// 128x128x16 smem-tiled fp32 GEMM, 8x8 microtiles, 256 threads.
// ============================================================
#define HT 256
__global__ __launch_bounds__(HT, 2)
void head_kernel(const float* __restrict__ E, float* __restrict__ out) {
    __shared__ __align__(16) float As[16][128 + 4];
    __shared__ __align__(16) float Bs[16][128 + 4];
    const float* __restrict__ Y = g_y;
    const int m0 = blockIdx.y * 128;
    const int n0 = blockIdx.x * 128;
    const int tid = threadIdx.x;
    const int tx = tid & 15, ty = tid >> 4;

    float c[8][8];
#pragma unroll
    for (int i = 0; i < 8; i++)
#pragma unroll
        for (int jj = 0; jj < 8; jj++) c[i][jj] = 0.f;

    for (int kk = 0; kk < RD; kk += 16) {
#pragma unroll
        for (int l = 0; l < 2; l++) {
            int idx = tid + l * HT;
            int m   = idx >> 2;
            int kq  = idx & 3;
            float4 av = *(const float4*)(Y + (size_t)(m0 + m) * RD + kk + kq * 4);
            As[kq * 4 + 0][m] = av.x; As[kq * 4 + 1][m] = av.y;
            As[kq * 4 + 2][m] = av.z; As[kq * 4 + 3][m] = av.w;
            float4 bv = *(const float4*)(E + (size_t)(n0 + m) * RD + kk + kq * 4);
            Bs[kq * 4 + 0][m] = bv.x; Bs[kq * 4 + 1][m] = bv.y;
            Bs[kq * 4 + 2][m] = bv.z; Bs[kq * 4 + 3][m] = bv.w;
        }
        __syncthreads();
#pragma unroll
        for (int k = 0; k < 16; k++) {
            float a[8], bb[8];
            *(float4*)(a)      = *(const float4*)(&As[k][ty * 8]);
            *(float4*)(a + 4)  = *(const float4*)(&As[k][ty * 8 + 4]);
            *(float4*)(bb)     = *(const float4*)(&Bs[k][tx * 8]);
            *(float4*)(bb + 4) = *(const float4*)(&Bs[k][tx * 8 + 4]);
#pragma unroll
            for (int i = 0; i < 8; i++)
#pragma unroll
                for (int jj = 0; jj < 8; jj++) c[i][jj] += a[i] * bb[jj];
        }
        __syncthreads();
    }
#pragma unroll
    for (int i = 0; i < 8; i++) {
        float* orow = out + (size_t)(m0 + ty * 8 + i) * RV + n0 + tx * 8;
        *(float4*)(orow)     = make_float4(c[i][0], c[i][1], c[i][2], c[i][3]);
        *(float4*)(orow + 4) = make_float4(c[i][4], c[i][5], c[i][6], c[i][7]);
    }
}

// ============================================================
extern "C" void kernel_launch(void* const* d_in, const int* in_sizes, int n_in,
                              void* d_out, int out_size) {
    const int*   tokens = (const int*)  d_in[0];
    const float* E      = (const float*)d_in[1];
    const float* Wxw    = (const float*)d_in[2];
    const float* Whw    = (const float*)d_in[3];
    const float* Wzw    = (const float*)d_in[4];
    float* out = (float*)d_out;

    cudaFuncSetAttribute(scan_kernel,
                         cudaFuncAttributeMaxDynamicSharedMemorySize,
                         SCAN_PAD_BYTES);

    precompute_kernel<<<2 * RV, RD>>>(E, Wxw, Wzw);
    scan_kernel<<<2 * RB, SCAN_THREADS, SCAN_PAD_BYTES>>>(tokens, Whw);
    head_kernel<<<dim3(RV / 128, (RB * RT) / 128), HT>>>(E, out);
}